// round 13
// baseline (speedup 1.0000x reference)
#include <cuda_runtime.h>
#include <cstdint>

// ---------------- problem dims ----------------
#define T_STEPS 256
#define B_DIM   64
#define F_DIM   1024
#define M_TOT   16384           // T*B
#define N_TOT   1024
#define K_IN    1024

// ---------------- GEMM tiling (int8) ----------------
#define TILE_M  128
#define TILE_N  256
#define TILE_K  128             // int8 elems = bytes per row-tile
#define NKT     (K_IN / TILE_K) // 8 per slice, 16 total
#define THREADS 512
#define A_KT_BYTES    (TILE_M * TILE_K)   // 16384
#define A_PANEL_BYTES (TILE_M * K_IN)     // 131072 (resident A panel)
#define B_STAGE_BYTES (TILE_N * TILE_K)   // 32768
#define B_STAGES 3
#define SMEM_TOTAL (A_PANEL_BYTES + B_STAGES * B_STAGE_BYTES)  // 229376

// SW128 swizzle on byte offsets (rows are 128B)
#define SWZ(x) ((x) ^ (((x) >> 3) & 0x70))

// ---------------- device scratch (allocation-free) ----------------
__device__ __align__(1024) uint8_t g_X  [(size_t)M_TOT * K_IN];
__device__ __align__(1024) int8_t  g_Whi[(size_t)N_TOT * K_IN];
__device__ __align__(1024) uint8_t g_Wlo[(size_t)N_TOT * K_IN];
__device__ __align__(1024) float   g_scale[N_TOT];
__device__ __align__(1024) float   g_cur[(size_t)M_TOT * N_TOT];

// ---------------- PTX helpers ----------------
__device__ __forceinline__ uint32_t smem_u32(const void* p) {
    uint32_t a;
    asm("{ .reg .u64 t; cvta.to.shared.u64 t, %1; cvt.u32.u64 %0, t; }"
        : "=r"(a) : "l"(p));
    return a;
}

#define CP_ASYNC16(dst, src) \
    asm volatile("cp.async.cg.shared.global [%0], [%1], 16;" \
                 :: "r"(dst), "l"(src) : "memory")
#define CP_COMMIT() asm volatile("cp.async.commit_group;" ::: "memory")
#define CP_WAIT(n)  asm volatile("cp.async.wait_group %0;" :: "n"(n) : "memory")

#define LDSM_X4(r0, r1, r2, r3, addr) \
    asm volatile("ldmatrix.sync.aligned.m8n8.x4.shared.b16 {%0,%1,%2,%3}, [%4];" \
                 : "=r"(r0), "=r"(r1), "=r"(r2), "=r"(r3) : "r"(addr))

// int8 tensor-core MMA, exact s32 accumulation. A = X (u8), B = W slice.
#define MMA_U8S8(c, a, b0, b1) \
    asm volatile("mma.sync.aligned.m16n8k32.row.col.s32.u8.s8.s32 " \
                 "{%0,%1,%2,%3}, {%4,%5,%6,%7}, {%8,%9}, {%0,%1,%2,%3};" \
                 : "+r"((c)[0]), "+r"((c)[1]), "+r"((c)[2]), "+r"((c)[3]) \
                 : "r"((a)[0]), "r"((a)[1]), "r"((a)[2]), "r"((a)[3]), \
                   "r"(b0), "r"(b1))
#define MMA_U8U8(c, a, b0, b1) \
    asm volatile("mma.sync.aligned.m16n8k32.row.col.s32.u8.u8.s32 " \
                 "{%0,%1,%2,%3}, {%4,%5,%6,%7}, {%8,%9}, {%0,%1,%2,%3};" \
                 : "+r"((c)[0]), "+r"((c)[1]), "+r"((c)[2]), "+r"((c)[3]) \
                 : "r"((a)[0]), "r"((a)[1]), "r"((a)[2]), "r"((a)[3]), \
                   "r"(b0), "r"(b1))

// ---------------- kernel 0: spikes fp32 -> u8 (exact: 0/1) ----------------
__global__ void __launch_bounds__(256) cvtX_kernel(const float4* __restrict__ in,
                                                   uchar4* __restrict__ out, int n4) {
    int i = blockIdx.x * blockDim.x + threadIdx.x;
    if (i < n4) {
        float4 f = __ldcs(in + i);   // read-once stream: don't pollute L2
        out[i] = make_uchar4((uint8_t)f.x, (uint8_t)f.y, (uint8_t)f.z, (uint8_t)f.w);
    }
}

// ---------------- kernel 1: per-row int16 quantization -> 2 int8 slices ------
// s_g = absmax(W[g,:]) / 32767 ;  q = rint(w / s_g) in [-32767, 32767]
// q = 256*q_hi + q_lo  with  q_hi = q >> 8 (floor, s8), q_lo in [0,255] (u8).
// Exact split; GEMM over integer slices accumulates EXACTLY in s32.
__global__ void __launch_bounds__(256) quantW_kernel(const float* __restrict__ W,
                                                     int8_t*  __restrict__ whi,
                                                     uint8_t* __restrict__ wlo,
                                                     float* __restrict__ scales) {
    __shared__ float red[256];
    __shared__ float s_sh;
    const int g   = blockIdx.x;
    const int tid = threadIdx.x;
    const float* row = W + (size_t)g * K_IN;

    float m = 0.0f;
    #pragma unroll
    for (int i = 0; i < K_IN / 256; i++)
        m = fmaxf(m, fabsf(row[tid + i * 256]));
    red[tid] = m;
    __syncthreads();
    for (int s = 128; s > 0; s >>= 1) {
        if (tid < s) red[tid] = fmaxf(red[tid], red[tid + s]);
        __syncthreads();
    }
    if (tid == 0) {
        float sc = red[0] / 32767.0f;
        s_sh = sc;
        scales[g] = sc;
    }
    __syncthreads();
    const float s = s_sh;

    #pragma unroll
    for (int i = 0; i < K_IN / 256; i++) {
        int k = tid + i * 256;
        int qi = (int)rintf(row[k] / s);      // |qi| <= 32767
        int hi = qi >> 8;                      // floor; in [-128, 127]
        int lo = qi - (hi << 8);               // in [0, 255]
        whi[(size_t)g * K_IN + k] = (int8_t)hi;
        wlo[(size_t)g * K_IN + k] = (uint8_t)lo;
    }
}

// ---------------- kernel 2: int8 tensor-core GEMM (3-stage B pipeline) -------
// S[m][g] = sum_k X[m][k] * q[g][k]  (exact s32):
//   ktg 0..7  : hi slice MMAs           (acc = S_hi)
//   boundary  : acc *= 256              (exact, |acc|*256 < 2^31)
//   ktg 8..15 : lo slice MMAs           (acc = 256*S_hi + S_lo = S)
// cur = float(S) * s_g  (one dequant rounding; bit-identical to R7 path).
// Pipeline: one barrier per iteration, prefetch depth 2 B tiles.

__device__ __forceinline__ void load_B_stage(uint32_t sB, int stage, int kt,
                                             const uint8_t* __restrict__ Bg,
                                             int nBase, int tid) {
    // 256 rows x 128B = 2048 x 16B chunks, 4 per thread
    #pragma unroll
    for (int i = 0; i < (TILE_N * 8) / THREADS; i++) {
        int c = tid + i * THREADS;
        int r = c >> 3, c8 = c & 7;
        const void* g = Bg + (size_t)(nBase + r) * K_IN + kt * TILE_K + c8 * 16;
        uint32_t d = sB + stage * B_STAGE_BYTES + SWZ(r * 128 + c8 * 16);
        CP_ASYNC16(d, g);
    }
}

__global__ void __launch_bounds__(THREADS, 1) gemm_i8_kernel(
    const uint8_t* __restrict__ X,
    const int8_t*  __restrict__ Whi,
    const uint8_t* __restrict__ Wlo,
    const float*   __restrict__ scales,
    float* __restrict__ cur) {
    extern __shared__ char smem[];
    const uint32_t sA = smem_u32(smem);
    const uint32_t sB = sA + A_PANEL_BYTES;
    const int tid  = threadIdx.x;
    const int wid  = tid >> 5;
    const int lane = tid & 31;
    const int mBase = blockIdx.y * TILE_M;
    const int nBase = blockIdx.x * TILE_N;

    const int wm = (wid >> 2) * 32;   // warp row in tile (4 warps in M)
    const int wn = (wid & 3) * 64;    // warp col in tile (4 warps in N)

    // ---- load resident A panel: 128 rows x 1024B, tiled per kt ----
    #pragma unroll
    for (int i = 0; i < (TILE_M * K_IN / 16) / THREADS; i++) {
        int c = tid + i * THREADS;               // 0..8191
        int kt = c >> 10, r = (c >> 3) & 127, c8 = c & 7;
        const void* g = X + (size_t)(mBase + r) * K_IN + kt * TILE_K + c8 * 16;
        uint32_t d = sA + kt * A_KT_BYTES + SWZ(r * 128 + c8 * 16);
        CP_ASYNC16(d, g);
    }
    CP_COMMIT();                                 // group: A panel

    const int a_row = lane & 15;
    const int a_k16 = (lane >> 4) * 16;
    const int b_row = (lane & 7) + ((lane >> 4) << 3);
    const int b_k16 = ((lane >> 3) & 1) * 16;

    int acc[2][8][4] = {};

    // prologue: B stages 0 and 1 in flight (hi slice kt 0, 1)
    load_B_stage(sB, 0, 0, (const uint8_t*)Whi, nBase, tid);
    CP_COMMIT();
    load_B_stage(sB, 1, 1, (const uint8_t*)Whi, nBase, tid);
    CP_COMMIT();

    for (int ktg = 0; ktg < 2 * NKT; ktg++) {
        // stage ktg ready (all but the newest 1 group complete; iter 0 also
        // completes the A-panel group since groups retire in order)
        if (ktg == 2 * NKT - 1) { CP_WAIT(0); } else { CP_WAIT(1); }
        __syncthreads();   // also: all warps done computing ktg-1 -> safe to
                           // overwrite buffer (ktg+2)%3 == (ktg-1)%3 below

        int nk = ktg + 2;
        if (nk < 2 * NKT) {
            const uint8_t* src = (nk < NKT) ? (const uint8_t*)Whi : Wlo;
            load_B_stage(sB, nk % B_STAGES, nk & (NKT - 1), src, nBase, tid);
            CP_COMMIT();
        }

        const uint32_t aBase = sA + (ktg & (NKT - 1)) * A_KT_BYTES;
        const uint32_t bBase = sB + (ktg % B_STAGES) * B_STAGE_BYTES;
        const bool hiPass = (ktg < NKT);

        #pragma unroll
        for (int kb = 0; kb < 4; kb++) {      // 4 x k32 per 128B tile
            uint32_t a[2][4], b[4][4];
            #pragma unroll
            for (int mt = 0; mt < 2; mt++) {
                uint32_t addr = aBase +
                    SWZ((wm + mt * 16 + a_row) * 128 + kb * 32 + a_k16);
                LDSM_X4(a[mt][0], a[mt][1], a[mt][2], a[mt][3], addr);
            }
            #pragma unroll
            for (int np = 0; np < 4; np++) {  // each x4 covers 2 n8-tiles
                uint32_t addr = bBase +
                    SWZ((wn + np * 16 + b_row) * 128 + kb * 32 + b_k16);
                LDSM_X4(b[np][0], b[np][1], b[np][2], b[np][3], addr);
            }
            if (hiPass) {
                #pragma unroll
                for (int mt = 0; mt < 2; mt++)
                    #pragma unroll
                    for (int nt = 0; nt < 8; nt++)
                        MMA_U8S8(acc[mt][nt], a[mt],
                                 b[nt >> 1][(nt & 1) * 2], b[nt >> 1][(nt & 1) * 2 + 1]);
            } else {
                #pragma unroll
                for (int mt = 0; mt < 2; mt++)
                    #pragma unroll
                    for (int nt = 0; nt < 8; nt++)
                        MMA_U8U8(acc[mt][nt], a[mt],
                                 b[nt >> 1][(nt & 1) * 2], b[nt >> 1][(nt & 1) * 2 + 1]);
            }
        }

        if (ktg == NKT - 1) {
            // acc = 256 * S_hi  (exact: |S_hi| <= 2^17, *256 < 2^31)
            #pragma unroll
            for (int mt = 0; mt < 2; mt++)
                #pragma unroll
                for (int nt = 0; nt < 8; nt++)
                    #pragma unroll
                    for (int q = 0; q < 4; q++) acc[mt][nt][q] *= 256;
        }
    }

    // epilogue: dequant + coalesced float2 stores (registers only; no sync)
    const int r0 = mBase + wm + (lane >> 2);
    const int c0 = nBase + wn + (lane & 3) * 2;
    #pragma unroll
    for (int mt = 0; mt < 2; mt++) {
        #pragma unroll
        for (int nt = 0; nt < 8; nt++) {
            int row = r0 + mt * 16;
            int col = c0 + nt * 8;
            float s0 = scales[col];
            float s1 = scales[col + 1];
            float2* p0 = reinterpret_cast<float2*>(cur + (size_t)row * N_TOT + col);
            float2* p1 = reinterpret_cast<float2*>(cur + (size_t)(row + 8) * N_TOT + col);
            *p0 = make_float2(__int2float_rn(acc[mt][nt][0]) * s0,
                              __int2float_rn(acc[mt][nt][1]) * s1);
            *p1 = make_float2(__int2float_rn(acc[mt][nt][2]) * s0,
                              __int2float_rn(acc[mt][nt][3]) * s1);
        }
    }
}

// ---------------- kernel 3: LIF scan over T (proven R7 version) ----------
__global__ void __launch_bounds__(256) lif_scan_kernel(const float* __restrict__ cur,
                                                       float* __restrict__ out) {
    int idx = blockIdx.x * blockDim.x + threadIdx.x;   // neuron id, 0..65535
    const float* p = cur + idx;
    float* o = out + idx;
    float v = 0.0f;
    #pragma unroll 8
    for (int t = 0; t < T_STEPS; ++t) {
        float x = p[(size_t)t * (B_DIM * F_DIM)];
        float t0 = x - v;
        v = fmaf(t0, 0.5f, v);                 // == v + (x - v)/2 bitwise
        float s = (v >= 1.0f) ? 1.0f : 0.0f;   // == (v - 1 >= 0) (Sterbenz)
        o[(size_t)t * (B_DIM * F_DIM)] = s;
        if (v >= 1.0f) v = 0.0f;               // hard reset, (1-s)*v
    }
}

// ---------------- host launcher ----------------
extern "C" void kernel_launch(void* const* d_in, const int* in_sizes, int n_in,
                              void* d_out, int out_size) {
    const float* X = (const float*)d_in[0];   // [T,B,F] spikes fp32
    const float* W = (const float*)d_in[1];   // [F,F] fp32
    if (n_in >= 2 && in_sizes[0] == N_TOT * K_IN && in_sizes[1] == M_TOT * K_IN) {
        const float* tmp = X; X = W; W = tmp;  // order guard
    }
    float* out = (float*)d_out;

    void *pX = nullptr, *pWh = nullptr, *pWl = nullptr, *pS = nullptr, *pC = nullptr;
    cudaGetSymbolAddress(&pX, g_X);
    cudaGetSymbolAddress(&pWh, g_Whi);
    cudaGetSymbolAddress(&pWl, g_Wlo);
    cudaGetSymbolAddress(&pS, g_scale);
    cudaGetSymbolAddress(&pC, g_cur);

    quantW_kernel<<<N_TOT, 256>>>(W, (int8_t*)pWh, (uint8_t*)pWl, (float*)pS);
    cvtX_kernel<<<(M_TOT * K_IN / 4 + 255) / 256, 256>>>(
        (const float4*)X, (uchar4*)pX, M_TOT * K_IN / 4);

    cudaFuncSetAttribute(gemm_i8_kernel, cudaFuncAttributeMaxDynamicSharedMemorySize,
                         SMEM_TOTAL);
    gemm_i8_kernel<<<dim3(N_TOT / TILE_N, M_TOT / TILE_M), THREADS, SMEM_TOTAL>>>(
        (const uint8_t*)pX, (const int8_t*)pWh, (const uint8_t*)pWl,
        (const float*)pS, (float*)pC);

    lif_scan_kernel<<<(B_DIM * F_DIM) / 256, 256>>>((const float*)pC, out);
}

// round 14
// speedup vs baseline: 1.1175x; 1.1175x over previous
#include <cuda_runtime.h>
#include <cstdint>

// ---------------- problem dims ----------------
#define T_STEPS 256
#define B_DIM   64
#define F_DIM   1024
#define M_TOT   16384           // T*B
#define N_TOT   1024
#define K_IN    1024

// ---------------- GEMM tiling (int8, 2 CTAs/SM) ----------------
#define TILE_M  128
#define TILE_N  128
#define TILE_K  128             // int8 elems = bytes per row-tile
#define NKT     (K_IN / TILE_K) // 8 per slice, 16 total
#define THREADS 256
#define A_STAGE_BYTES (TILE_M * TILE_K)   // 16384
#define B_STAGE_BYTES (TILE_N * TILE_K)   // 16384
#define STAGE_BYTES   (A_STAGE_BYTES + B_STAGE_BYTES)   // 32768
#define B_STAGES 3
#define SMEM_TOTAL (B_STAGES * STAGE_BYTES)             // 98304 -> 2 CTAs/SM

// SW128 swizzle on byte offsets (rows are 128B)
#define SWZ(x) ((x) ^ (((x) >> 3) & 0x70))

// ---------------- device scratch (allocation-free) ----------------
__device__ __align__(1024) uint8_t g_X  [(size_t)M_TOT * K_IN];
__device__ __align__(1024) int8_t  g_Whi[(size_t)N_TOT * K_IN];
__device__ __align__(1024) uint8_t g_Wlo[(size_t)N_TOT * K_IN];
__device__ __align__(1024) float   g_scale[N_TOT];
__device__ __align__(1024) float   g_cur[(size_t)M_TOT * N_TOT];

// ---------------- PTX helpers ----------------
__device__ __forceinline__ uint32_t smem_u32(const void* p) {
    uint32_t a;
    asm("{ .reg .u64 t; cvta.to.shared.u64 t, %1; cvt.u32.u64 %0, t; }"
        : "=r"(a) : "l"(p));
    return a;
}

#define CP_ASYNC16(dst, src) \
    asm volatile("cp.async.cg.shared.global [%0], [%1], 16;" \
                 :: "r"(dst), "l"(src) : "memory")
#define CP_COMMIT() asm volatile("cp.async.commit_group;" ::: "memory")
#define CP_WAIT(n)  asm volatile("cp.async.wait_group %0;" :: "n"(n) : "memory")

#define LDSM_X4(r0, r1, r2, r3, addr) \
    asm volatile("ldmatrix.sync.aligned.m8n8.x4.shared.b16 {%0,%1,%2,%3}, [%4];" \
                 : "=r"(r0), "=r"(r1), "=r"(r2), "=r"(r3) : "r"(addr))

// int8 tensor-core MMA, exact s32 accumulation. A = X (u8), B = W slice.
#define MMA_U8S8(c, a, b0, b1) \
    asm volatile("mma.sync.aligned.m16n8k32.row.col.s32.u8.s8.s32 " \
                 "{%0,%1,%2,%3}, {%4,%5,%6,%7}, {%8,%9}, {%0,%1,%2,%3};" \
                 : "+r"((c)[0]), "+r"((c)[1]), "+r"((c)[2]), "+r"((c)[3]) \
                 : "r"((a)[0]), "r"((a)[1]), "r"((a)[2]), "r"((a)[3]), \
                   "r"(b0), "r"(b1))
#define MMA_U8U8(c, a, b0, b1) \
    asm volatile("mma.sync.aligned.m16n8k32.row.col.s32.u8.u8.s32 " \
                 "{%0,%1,%2,%3}, {%4,%5,%6,%7}, {%8,%9}, {%0,%1,%2,%3};" \
                 : "+r"((c)[0]), "+r"((c)[1]), "+r"((c)[2]), "+r"((c)[3]) \
                 : "r"((a)[0]), "r"((a)[1]), "r"((a)[2]), "r"((a)[3]), \
                   "r"(b0), "r"(b1))

// ---------------- kernel 0: spikes fp32 -> u8 (exact: 0/1) ----------------
__global__ void __launch_bounds__(256) cvtX_kernel(const float4* __restrict__ in,
                                                   uchar4* __restrict__ out, int n4) {
    int i = blockIdx.x * blockDim.x + threadIdx.x;
    if (i < n4) {
        float4 f = __ldcs(in + i);   // read-once stream: don't pollute L2
        out[i] = make_uchar4((uint8_t)f.x, (uint8_t)f.y, (uint8_t)f.z, (uint8_t)f.w);
    }
}

// ---------------- kernel 1: per-row int16 quantization -> 2 int8 slices ------
// s_g = absmax(W[g,:]) / 32767 ;  q = rint(w / s_g) in [-32767, 32767]
// q = 256*q_hi + q_lo  with  q_hi = q >> 8 (floor, s8), q_lo in [0,255] (u8).
// Exact split; GEMM over integer slices accumulates EXACTLY in s32.
__global__ void __launch_bounds__(256) quantW_kernel(const float* __restrict__ W,
                                                     int8_t*  __restrict__ whi,
                                                     uint8_t* __restrict__ wlo,
                                                     float* __restrict__ scales) {
    __shared__ float red[256];
    __shared__ float s_sh;
    const int g   = blockIdx.x;
    const int tid = threadIdx.x;
    const float* row = W + (size_t)g * K_IN;

    float m = 0.0f;
    #pragma unroll
    for (int i = 0; i < K_IN / 256; i++)
        m = fmaxf(m, fabsf(row[tid + i * 256]));
    red[tid] = m;
    __syncthreads();
    for (int s = 128; s > 0; s >>= 1) {
        if (tid < s) red[tid] = fmaxf(red[tid], red[tid + s]);
        __syncthreads();
    }
    if (tid == 0) {
        float sc = red[0] / 32767.0f;
        s_sh = sc;
        scales[g] = sc;
    }
    __syncthreads();
    const float s = s_sh;

    #pragma unroll
    for (int i = 0; i < K_IN / 256; i++) {
        int k = tid + i * 256;
        int qi = (int)rintf(row[k] / s);      // |qi| <= 32767
        int hi = qi >> 8;                      // floor; in [-128, 127]
        int lo = qi - (hi << 8);               // in [0, 255]
        whi[(size_t)g * K_IN + k] = (int8_t)hi;
        wlo[(size_t)g * K_IN + k] = (uint8_t)lo;
    }
}

// ---------------- kernel 2: int8 tensor-core GEMM (128x128, 2 CTAs/SM) -------
// S[m][g] = sum_k X[m][k] * q[g][k]  (exact s32):
//   ktg 0..7  : hi slice MMAs           (acc = S_hi)
//   boundary  : acc *= 256              (exact, |acc|*256 < 2^31)
//   ktg 8..15 : lo slice MMAs           (acc = 256*S_hi + S_lo = S)
// cur = float(S) * s_g  (one dequant rounding; bit-identical to R7 path).
// A and B both streamed, 3 stages, one barrier per iteration.

__device__ __forceinline__ void load_stage(uint32_t sS, int stage, int ktg,
                                           const uint8_t* __restrict__ X,
                                           const uint8_t* __restrict__ Bg,
                                           int mBase, int nBase, int tid) {
    const int kOff = (ktg & (NKT - 1)) * TILE_K;
    const uint32_t base = sS + stage * STAGE_BYTES;
    // A: 128 rows x 8 x 16B chunks = 1024 chunks, 4 per thread
    #pragma unroll
    for (int i = 0; i < (TILE_M * 8) / THREADS; i++) {
        int c = tid + i * THREADS;
        int r = c >> 3, c8 = c & 7;
        const void* g = X + (size_t)(mBase + r) * K_IN + kOff + c8 * 16;
        CP_ASYNC16(base + SWZ(r * 128 + c8 * 16), g);
    }
    // B: 128 rows x 8 chunks = 1024 chunks, 4 per thread
    #pragma unroll
    for (int i = 0; i < (TILE_N * 8) / THREADS; i++) {
        int c = tid + i * THREADS;
        int r = c >> 3, c8 = c & 7;
        const void* g = Bg + (size_t)(nBase + r) * K_IN + kOff + c8 * 16;
        CP_ASYNC16(base + A_STAGE_BYTES + SWZ(r * 128 + c8 * 16), g);
    }
}

__global__ void __launch_bounds__(THREADS, 2) gemm_i8_kernel(
    const uint8_t* __restrict__ X,
    const int8_t*  __restrict__ Whi,
    const uint8_t* __restrict__ Wlo,
    const float*   __restrict__ scales,
    float* __restrict__ cur) {
    extern __shared__ char smem[];
    const uint32_t sS = smem_u32(smem);
    const int tid  = threadIdx.x;
    const int wid  = tid >> 5;
    const int lane = tid & 31;
    const int mBase = blockIdx.y * TILE_M;
    const int nBase = blockIdx.x * TILE_N;

    const int wm = (wid >> 2) * 64;   // warp row (2 warps in M, 64 rows each)
    const int wn = (wid & 3) * 32;    // warp col (4 warps in N, 32 cols each)

    const int a_row = lane & 15;
    const int a_k16 = (lane >> 4) * 16;
    const int b_row = (lane & 7) + ((lane >> 4) << 3);
    const int b_k16 = ((lane >> 3) & 1) * 16;

    int acc[4][4][4] = {};

    // prologue: stages 0 and 1 in flight (hi slice ktg 0, 1)
    load_stage(sS, 0, 0, X, (const uint8_t*)Whi, mBase, nBase, tid);
    CP_COMMIT();
    load_stage(sS, 1, 1, X, (const uint8_t*)Whi, mBase, nBase, tid);
    CP_COMMIT();

    for (int ktg = 0; ktg < 2 * NKT; ktg++) {
        if (ktg == 2 * NKT - 1) { CP_WAIT(0); } else { CP_WAIT(1); }
        __syncthreads();   // all warps done with ktg-1 -> safe to overwrite
                           // stage (ktg+2)%3 == (ktg-1)%3 below

        int nk = ktg + 2;
        if (nk < 2 * NKT) {
            const uint8_t* src = (nk < NKT) ? (const uint8_t*)Whi : Wlo;
            load_stage(sS, nk % B_STAGES, nk, X, src, mBase, nBase, tid);
            CP_COMMIT();
        }

        const uint32_t aBase = sS + (ktg % B_STAGES) * STAGE_BYTES;
        const uint32_t bBase = aBase + A_STAGE_BYTES;
        const bool hiPass = (ktg < NKT);

        #pragma unroll
        for (int kb = 0; kb < 4; kb++) {      // 4 x k32 per 128B tile
            uint32_t a[4][4], b[2][4];
            #pragma unroll
            for (int mt = 0; mt < 4; mt++) {
                uint32_t addr = aBase +
                    SWZ((wm + mt * 16 + a_row) * 128 + kb * 32 + a_k16);
                LDSM_X4(a[mt][0], a[mt][1], a[mt][2], a[mt][3], addr);
            }
            #pragma unroll
            for (int np = 0; np < 2; np++) {  // each x4 covers 2 n8-tiles
                uint32_t addr = bBase +
                    SWZ((wn + np * 16 + b_row) * 128 + kb * 32 + b_k16);
                LDSM_X4(b[np][0], b[np][1], b[np][2], b[np][3], addr);
            }
            if (hiPass) {
                #pragma unroll
                for (int mt = 0; mt < 4; mt++)
                    #pragma unroll
                    for (int nt = 0; nt < 4; nt++)
                        MMA_U8S8(acc[mt][nt], a[mt],
                                 b[nt >> 1][(nt & 1) * 2], b[nt >> 1][(nt & 1) * 2 + 1]);
            } else {
                #pragma unroll
                for (int mt = 0; mt < 4; mt++)
                    #pragma unroll
                    for (int nt = 0; nt < 4; nt++)
                        MMA_U8U8(acc[mt][nt], a[mt],
                                 b[nt >> 1][(nt & 1) * 2], b[nt >> 1][(nt & 1) * 2 + 1]);
            }
        }

        if (ktg == NKT - 1) {
            // acc = 256 * S_hi  (exact: |S_hi| <= 2^17, *256 < 2^31)
            #pragma unroll
            for (int mt = 0; mt < 4; mt++)
                #pragma unroll
                for (int nt = 0; nt < 4; nt++)
                    #pragma unroll
                    for (int q = 0; q < 4; q++) acc[mt][nt][q] *= 256;
        }
    }

    // epilogue: dequant + coalesced float2 stores (registers only; no sync)
    const int r0 = mBase + wm + (lane >> 2);
    const int c0 = nBase + wn + (lane & 3) * 2;
    #pragma unroll
    for (int mt = 0; mt < 4; mt++) {
        #pragma unroll
        for (int nt = 0; nt < 4; nt++) {
            int row = r0 + mt * 16;
            int col = c0 + nt * 8;
            float s0 = scales[col];
            float s1 = scales[col + 1];
            float2* p0 = reinterpret_cast<float2*>(cur + (size_t)row * N_TOT + col);
            float2* p1 = reinterpret_cast<float2*>(cur + (size_t)(row + 8) * N_TOT + col);
            *p0 = make_float2(__int2float_rn(acc[mt][nt][0]) * s0,
                              __int2float_rn(acc[mt][nt][1]) * s1);
            *p1 = make_float2(__int2float_rn(acc[mt][nt][2]) * s0,
                              __int2float_rn(acc[mt][nt][3]) * s1);
        }
    }
}

// ---------------- kernel 3: LIF scan over T (proven R7 version) ----------
__global__ void __launch_bounds__(256) lif_scan_kernel(const float* __restrict__ cur,
                                                       float* __restrict__ out) {
    int idx = blockIdx.x * blockDim.x + threadIdx.x;   // neuron id, 0..65535
    const float* p = cur + idx;
    float* o = out + idx;
    float v = 0.0f;
    #pragma unroll 8
    for (int t = 0; t < T_STEPS; ++t) {
        float x = p[(size_t)t * (B_DIM * F_DIM)];
        float t0 = x - v;
        v = fmaf(t0, 0.5f, v);                 // == v + (x - v)/2 bitwise
        float s = (v >= 1.0f) ? 1.0f : 0.0f;   // == (v - 1 >= 0) (Sterbenz)
        o[(size_t)t * (B_DIM * F_DIM)] = s;
        if (v >= 1.0f) v = 0.0f;               // hard reset, (1-s)*v
    }
}

// ---------------- host launcher ----------------
extern "C" void kernel_launch(void* const* d_in, const int* in_sizes, int n_in,
                              void* d_out, int out_size) {
    const float* X = (const float*)d_in[0];   // [T,B,F] spikes fp32
    const float* W = (const float*)d_in[1];   // [F,F] fp32
    if (n_in >= 2 && in_sizes[0] == N_TOT * K_IN && in_sizes[1] == M_TOT * K_IN) {
        const float* tmp = X; X = W; W = tmp;  // order guard
    }
    float* out = (float*)d_out;

    void *pX = nullptr, *pWh = nullptr, *pWl = nullptr, *pS = nullptr, *pC = nullptr;
    cudaGetSymbolAddress(&pX, g_X);
    cudaGetSymbolAddress(&pWh, g_Whi);
    cudaGetSymbolAddress(&pWl, g_Wlo);
    cudaGetSymbolAddress(&pS, g_scale);
    cudaGetSymbolAddress(&pC, g_cur);

    quantW_kernel<<<N_TOT, 256>>>(W, (int8_t*)pWh, (uint8_t*)pWl, (float*)pS);
    cvtX_kernel<<<(M_TOT * K_IN / 4 + 255) / 256, 256>>>(
        (const float4*)X, (uchar4*)pX, M_TOT * K_IN / 4);

    cudaFuncSetAttribute(gemm_i8_kernel, cudaFuncAttributeMaxDynamicSharedMemorySize,
                         SMEM_TOTAL);
    gemm_i8_kernel<<<dim3(N_TOT / TILE_N, M_TOT / TILE_M), THREADS, SMEM_TOTAL>>>(
        (const uint8_t*)pX, (const int8_t*)pWh, (const uint8_t*)pWl,
        (const float*)pS, (float*)pC);

    lif_scan_kernel<<<(B_DIM * F_DIM) / 256, 256>>>((const float*)pC, out);
}

// round 15
// speedup vs baseline: 1.1719x; 1.0487x over previous
#include <cuda_runtime.h>
#include <cstdint>

// ---------------- problem dims ----------------
#define T_STEPS 256
#define B_DIM   64
#define F_DIM   1024
#define M_TOT   16384           // T*B
#define N_TOT   1024
#define K_IN    1024

// ---------------- GEMM tiling (int8, fine-grain CTAs) ----------------
#define TILE_M  128
#define TILE_N  64
#define TILE_K  128             // int8 elems = bytes per row-tile
#define NKT     (K_IN / TILE_K) // 8 per slice, 16 total
#define THREADS 256
#define A_STAGE_BYTES (TILE_M * TILE_K)   // 16384
#define B_STAGE_BYTES (TILE_N * TILE_K)   // 8192
#define STAGE_BYTES   (A_STAGE_BYTES + B_STAGE_BYTES)   // 24576
#define B_STAGES 3
#define SMEM_TOTAL (B_STAGES * STAGE_BYTES)             // 73728

// SW128 swizzle on byte offsets (rows are 128B)
#define SWZ(x) ((x) ^ (((x) >> 3) & 0x70))

// ---------------- device scratch (allocation-free) ----------------
__device__ __align__(1024) uint8_t g_X  [(size_t)M_TOT * K_IN];
__device__ __align__(1024) int8_t  g_Whi[(size_t)N_TOT * K_IN];
__device__ __align__(1024) uint8_t g_Wlo[(size_t)N_TOT * K_IN];
__device__ __align__(1024) float   g_scale[N_TOT];
__device__ __align__(1024) float   g_cur[(size_t)M_TOT * N_TOT];

// ---------------- PTX helpers ----------------
__device__ __forceinline__ uint32_t smem_u32(const void* p) {
    uint32_t a;
    asm("{ .reg .u64 t; cvta.to.shared.u64 t, %1; cvt.u32.u64 %0, t; }"
        : "=r"(a) : "l"(p));
    return a;
}

#define CP_ASYNC16(dst, src) \
    asm volatile("cp.async.cg.shared.global [%0], [%1], 16;" \
                 :: "r"(dst), "l"(src) : "memory")
#define CP_COMMIT() asm volatile("cp.async.commit_group;" ::: "memory")
#define CP_WAIT(n)  asm volatile("cp.async.wait_group %0;" :: "n"(n) : "memory")

#define LDSM_X4(r0, r1, r2, r3, addr) \
    asm volatile("ldmatrix.sync.aligned.m8n8.x4.shared.b16 {%0,%1,%2,%3}, [%4];" \
                 : "=r"(r0), "=r"(r1), "=r"(r2), "=r"(r3) : "r"(addr))

// int8 tensor-core MMA, exact s32 accumulation. A = X (u8), B = W slice.
#define MMA_U8S8(c, a, b0, b1) \
    asm volatile("mma.sync.aligned.m16n8k32.row.col.s32.u8.s8.s32 " \
                 "{%0,%1,%2,%3}, {%4,%5,%6,%7}, {%8,%9}, {%0,%1,%2,%3};" \
                 : "+r"((c)[0]), "+r"((c)[1]), "+r"((c)[2]), "+r"((c)[3]) \
                 : "r"((a)[0]), "r"((a)[1]), "r"((a)[2]), "r"((a)[3]), \
                   "r"(b0), "r"(b1))
#define MMA_U8U8(c, a, b0, b1) \
    asm volatile("mma.sync.aligned.m16n8k32.row.col.s32.u8.u8.s32 " \
                 "{%0,%1,%2,%3}, {%4,%5,%6,%7}, {%8,%9}, {%0,%1,%2,%3};" \
                 : "+r"((c)[0]), "+r"((c)[1]), "+r"((c)[2]), "+r"((c)[3]) \
                 : "r"((a)[0]), "r"((a)[1]), "r"((a)[2]), "r"((a)[3]), \
                   "r"(b0), "r"(b1))

// ---------------- kernel 0: spikes fp32 -> u8 (exact: 0/1) ----------------
__global__ void __launch_bounds__(256) cvtX_kernel(const float4* __restrict__ in,
                                                   uchar4* __restrict__ out, int n4) {
    int i = blockIdx.x * blockDim.x + threadIdx.x;
    if (i < n4) {
        float4 f = __ldcs(in + i);   // read-once stream: don't pollute L2
        out[i] = make_uchar4((uint8_t)f.x, (uint8_t)f.y, (uint8_t)f.z, (uint8_t)f.w);
    }
}

// ---------------- kernel 1: per-row int16 quantization -> 2 int8 slices ------
// s_g = absmax(W[g,:]) / 32767 ;  q = rint(w / s_g) in [-32767, 32767]
// q = 256*q_hi + q_lo  with  q_hi = q >> 8 (floor, s8), q_lo in [0,255] (u8).
// Exact split; GEMM over integer slices accumulates EXACTLY in s32.
__global__ void __launch_bounds__(256) quantW_kernel(const float* __restrict__ W,
                                                     int8_t*  __restrict__ whi,
                                                     uint8_t* __restrict__ wlo,
                                                     float* __restrict__ scales) {
    __shared__ float red[256];
    __shared__ float s_sh;
    const int g   = blockIdx.x;
    const int tid = threadIdx.x;
    const float* row = W + (size_t)g * K_IN;

    float m = 0.0f;
    #pragma unroll
    for (int i = 0; i < K_IN / 256; i++)
        m = fmaxf(m, fabsf(row[tid + i * 256]));
    red[tid] = m;
    __syncthreads();
    for (int s = 128; s > 0; s >>= 1) {
        if (tid < s) red[tid] = fmaxf(red[tid], red[tid + s]);
        __syncthreads();
    }
    if (tid == 0) {
        float sc = red[0] / 32767.0f;
        s_sh = sc;
        scales[g] = sc;
    }
    __syncthreads();
    const float s = s_sh;

    #pragma unroll
    for (int i = 0; i < K_IN / 256; i++) {
        int k = tid + i * 256;
        int qi = (int)rintf(row[k] / s);      // |qi| <= 32767
        int hi = qi >> 8;                      // floor; in [-128, 127]
        int lo = qi - (hi << 8);               // in [0, 255]
        whi[(size_t)g * K_IN + k] = (int8_t)hi;
        wlo[(size_t)g * K_IN + k] = (uint8_t)lo;
    }
}

// ---------------- kernel 2: int8 tensor-core GEMM (128x64, fine tail) --------
// S[m][g] = sum_k X[m][k] * q[g][k]  (exact s32):
//   ktg 0..7  : hi slice MMAs           (acc = S_hi)
//   boundary  : acc *= 256              (exact, |acc|*256 < 2^31)
//   ktg 8..15 : lo slice MMAs           (acc = 256*S_hi + S_lo = S)
// cur = float(S) * s_g  (one dequant rounding; bit-identical to R7 path).
// A and B streamed, 3 stages, one barrier per iteration (R14-proven schedule).

__device__ __forceinline__ void load_stage(uint32_t sS, int stage, int ktg,
                                           const uint8_t* __restrict__ X,
                                           const uint8_t* __restrict__ Bg,
                                           int mBase, int nBase, int tid) {
    const int kOff = (ktg & (NKT - 1)) * TILE_K;
    const uint32_t base = sS + stage * STAGE_BYTES;
    // A: 128 rows x 8 x 16B chunks = 1024 chunks, 4 per thread
    #pragma unroll
    for (int i = 0; i < (TILE_M * 8) / THREADS; i++) {
        int c = tid + i * THREADS;
        int r = c >> 3, c8 = c & 7;
        const void* g = X + (size_t)(mBase + r) * K_IN + kOff + c8 * 16;
        CP_ASYNC16(base + SWZ(r * 128 + c8 * 16), g);
    }
    // B: 64 rows x 8 chunks = 512 chunks, 2 per thread
    #pragma unroll
    for (int i = 0; i < (TILE_N * 8) / THREADS; i++) {
        int c = tid + i * THREADS;
        int r = c >> 3, c8 = c & 7;
        const void* g = Bg + (size_t)(nBase + r) * K_IN + kOff + c8 * 16;
        CP_ASYNC16(base + A_STAGE_BYTES + SWZ(r * 128 + c8 * 16), g);
    }
}

__global__ void __launch_bounds__(THREADS, 2) gemm_i8_kernel(
    const uint8_t* __restrict__ X,
    const int8_t*  __restrict__ Whi,
    const uint8_t* __restrict__ Wlo,
    const float*   __restrict__ scales,
    float* __restrict__ cur) {
    extern __shared__ char smem[];
    const uint32_t sS = smem_u32(smem);
    const int tid  = threadIdx.x;
    const int wid  = tid >> 5;
    const int lane = tid & 31;
    const int mBase = blockIdx.y * TILE_M;
    const int nBase = blockIdx.x * TILE_N;

    const int wm = (wid >> 1) * 32;   // warp row (4 warps in M, 32 rows each)
    const int wn = (wid & 1) * 32;    // warp col (2 warps in N, 32 cols each)

    const int a_row = lane & 15;
    const int a_k16 = (lane >> 4) * 16;
    const int b_row = (lane & 7) + ((lane >> 4) << 3);
    const int b_k16 = ((lane >> 3) & 1) * 16;

    int acc[2][4][4] = {};

    // prologue: stages 0 and 1 in flight (hi slice ktg 0, 1)
    load_stage(sS, 0, 0, X, (const uint8_t*)Whi, mBase, nBase, tid);
    CP_COMMIT();
    load_stage(sS, 1, 1, X, (const uint8_t*)Whi, mBase, nBase, tid);
    CP_COMMIT();

    for (int ktg = 0; ktg < 2 * NKT; ktg++) {
        if (ktg == 2 * NKT - 1) { CP_WAIT(0); } else { CP_WAIT(1); }
        __syncthreads();   // all warps done with ktg-1 -> safe to overwrite
                           // stage (ktg+2)%3 == (ktg-1)%3 below

        int nk = ktg + 2;
        if (nk < 2 * NKT) {
            const uint8_t* src = (nk < NKT) ? (const uint8_t*)Whi : Wlo;
            load_stage(sS, nk % B_STAGES, nk, X, src, mBase, nBase, tid);
            CP_COMMIT();
        }

        const uint32_t aBase = sS + (ktg % B_STAGES) * STAGE_BYTES;
        const uint32_t bBase = aBase + A_STAGE_BYTES;
        const bool hiPass = (ktg < NKT);

        #pragma unroll
        for (int kb = 0; kb < 4; kb++) {      // 4 x k32 per 128B tile
            uint32_t a[2][4], b[2][4];
            #pragma unroll
            for (int mt = 0; mt < 2; mt++) {
                uint32_t addr = aBase +
                    SWZ((wm + mt * 16 + a_row) * 128 + kb * 32 + a_k16);
                LDSM_X4(a[mt][0], a[mt][1], a[mt][2], a[mt][3], addr);
            }
            #pragma unroll
            for (int np = 0; np < 2; np++) {  // each x4 covers 2 n8-tiles
                uint32_t addr = bBase +
                    SWZ((wn + np * 16 + b_row) * 128 + kb * 32 + b_k16);
                LDSM_X4(b[np][0], b[np][1], b[np][2], b[np][3], addr);
            }
            if (hiPass) {
                #pragma unroll
                for (int mt = 0; mt < 2; mt++)
                    #pragma unroll
                    for (int nt = 0; nt < 4; nt++)
                        MMA_U8S8(acc[mt][nt], a[mt],
                                 b[nt >> 1][(nt & 1) * 2], b[nt >> 1][(nt & 1) * 2 + 1]);
            } else {
                #pragma unroll
                for (int mt = 0; mt < 2; mt++)
                    #pragma unroll
                    for (int nt = 0; nt < 4; nt++)
                        MMA_U8U8(acc[mt][nt], a[mt],
                                 b[nt >> 1][(nt & 1) * 2], b[nt >> 1][(nt & 1) * 2 + 1]);
            }
        }

        if (ktg == NKT - 1) {
            // acc = 256 * S_hi  (exact: |S_hi| <= 2^17, *256 < 2^31)
            #pragma unroll
            for (int mt = 0; mt < 2; mt++)
                #pragma unroll
                for (int nt = 0; nt < 4; nt++)
                    #pragma unroll
                    for (int q = 0; q < 4; q++) acc[mt][nt][q] *= 256;
        }
    }

    // epilogue: dequant + coalesced float2 stores (registers only; no sync)
    const int r0 = mBase + wm + (lane >> 2);
    const int c0 = nBase + wn + (lane & 3) * 2;
    #pragma unroll
    for (int mt = 0; mt < 2; mt++) {
        #pragma unroll
        for (int nt = 0; nt < 4; nt++) {
            int row = r0 + mt * 16;
            int col = c0 + nt * 8;
            float s0 = scales[col];
            float s1 = scales[col + 1];
            float2* p0 = reinterpret_cast<float2*>(cur + (size_t)row * N_TOT + col);
            float2* p1 = reinterpret_cast<float2*>(cur + (size_t)(row + 8) * N_TOT + col);
            *p0 = make_float2(__int2float_rn(acc[mt][nt][0]) * s0,
                              __int2float_rn(acc[mt][nt][1]) * s1);
            *p1 = make_float2(__int2float_rn(acc[mt][nt][2]) * s0,
                              __int2float_rn(acc[mt][nt][3]) * s1);
        }
    }
}

// ---------------- kernel 3: LIF scan over T (proven math; deeper unroll) -----
__global__ void __launch_bounds__(256) lif_scan_kernel(const float* __restrict__ cur,
                                                       float* __restrict__ out) {
    int idx = blockIdx.x * blockDim.x + threadIdx.x;   // neuron id, 0..65535
    const float* p = cur + idx;
    float* o = out + idx;
    float v = 0.0f;
    #pragma unroll 16
    for (int t = 0; t < T_STEPS; ++t) {
        float x = p[(size_t)t * (B_DIM * F_DIM)];
        float t0 = x - v;
        v = fmaf(t0, 0.5f, v);                 // == v + (x - v)/2 bitwise
        float s = (v >= 1.0f) ? 1.0f : 0.0f;   // == (v - 1 >= 0) (Sterbenz)
        o[(size_t)t * (B_DIM * F_DIM)] = s;
        if (v >= 1.0f) v = 0.0f;               // hard reset, (1-s)*v
    }
}

// ---------------- host launcher ----------------
extern "C" void kernel_launch(void* const* d_in, const int* in_sizes, int n_in,
                              void* d_out, int out_size) {
    const float* X = (const float*)d_in[0];   // [T,B,F] spikes fp32
    const float* W = (const float*)d_in[1];   // [F,F] fp32
    if (n_in >= 2 && in_sizes[0] == N_TOT * K_IN && in_sizes[1] == M_TOT * K_IN) {
        const float* tmp = X; X = W; W = tmp;  // order guard
    }
    float* out = (float*)d_out;

    void *pX = nullptr, *pWh = nullptr, *pWl = nullptr, *pS = nullptr, *pC = nullptr;
    cudaGetSymbolAddress(&pX, g_X);
    cudaGetSymbolAddress(&pWh, g_Whi);
    cudaGetSymbolAddress(&pWl, g_Wlo);
    cudaGetSymbolAddress(&pS, g_scale);
    cudaGetSymbolAddress(&pC, g_cur);

    quantW_kernel<<<N_TOT, 256>>>(W, (int8_t*)pWh, (uint8_t*)pWl, (float*)pS);
    cvtX_kernel<<<(M_TOT * K_IN / 4 + 255) / 256, 256>>>(
        (const float4*)X, (uchar4*)pX, M_TOT * K_IN / 4);

    cudaFuncSetAttribute(gemm_i8_kernel, cudaFuncAttributeMaxDynamicSharedMemorySize,
                         SMEM_TOTAL);
    gemm_i8_kernel<<<dim3(N_TOT / TILE_N, M_TOT / TILE_M), THREADS, SMEM_TOTAL>>>(
        (const uint8_t*)pX, (const int8_t*)pWh, (const uint8_t*)pWl,
        (const float*)pS, (float*)pC);

    lif_scan_kernel<<<(B_DIM * F_DIM) / 256, 256>>>((const float*)pC, out);
}